// round 14
// baseline (speedup 1.0000x reference)
#include <cuda_runtime.h>
#include <cuda_bf16.h>
#include <cstdint>
#include <cstddef>

// ============================================================================
// Problem constants and scratch
// ============================================================================
static constexpr int DIM   = 1024;
static constexpr int H_MID = 512;
static constexpr int H_LOW = 256;
static constexpr int MTOT  = 4 * 8192;  // 32768 tokens

__device__ __nv_bfloat16 g_a0[(size_t)MTOT * DIM];    // ln_out, later h2
__device__ __nv_bfloat16 g_a1[(size_t)MTOT * H_MID];  // h1, later h3
__device__ __nv_bfloat16 g_w1t[H_MID * DIM];
__device__ __nv_bfloat16 g_w2t[H_MID * H_MID];
__device__ __nv_bfloat16 g_w3t[H_LOW * H_MID];
__device__ __nv_bfloat16 g_w4t[DIM * H_LOW];

// ============================================================================
// Helpers
// ============================================================================
__device__ __forceinline__ float gelu_exact(float v) {
    return 0.5f * v * (1.0f + erff(v * 0.70710678118654752440f));
}

__device__ __forceinline__ uint32_t smem_to_u32(const void* p) {
    uint32_t a;
    asm("{ .reg .u64 t; cvta.to.shared.u64 t, %1; cvt.u32.u64 %0, t; }"
        : "=r"(a) : "l"(p));
    return a;
}

__device__ __forceinline__ void cp_async16(uint32_t s, const void* g) {
    asm volatile("cp.async.cg.shared.global [%0], [%1], 16;" :: "r"(s), "l"(g));
}

__device__ __forceinline__ void ldsm_x4(uint32_t (&r)[4], uint32_t addr) {
    asm volatile("ldmatrix.sync.aligned.m8n8.x4.shared.b16 {%0,%1,%2,%3}, [%4];"
                 : "=r"(r[0]), "=r"(r[1]), "=r"(r[2]), "=r"(r[3]) : "r"(addr));
}

__device__ __forceinline__ void mma_bf16(float (&d)[4], const uint32_t (&a)[4],
                                         uint32_t b0, uint32_t b1) {
    asm volatile(
        "mma.sync.aligned.m16n8k16.row.col.f32.bf16.bf16.f32 "
        "{%0,%1,%2,%3},{%4,%5,%6,%7},{%8,%9},{%0,%1,%2,%3};"
        : "+f"(d[0]), "+f"(d[1]), "+f"(d[2]), "+f"(d[3])
        : "r"(a[0]), "r"(a[1]), "r"(a[2]), "r"(a[3]), "r"(b0), "r"(b1));
}

// ============================================================================
// All-weights transpose + bf16 round:  W[K,N] fp32 -> Wt[N,K] bf16
// ============================================================================
__device__ __forceinline__ void transpose_tile(const float* __restrict__ W,
                                               __nv_bfloat16* __restrict__ Wt,
                                               int K, int N, int tile,
                                               int tx, int ty) {
    __shared__ float t32[32][33];
    const int tilesX = N >> 5;
    const int n0 = (tile % tilesX) * 32, k0 = (tile / tilesX) * 32;
#pragma unroll
    for (int j = 0; j < 32; j += 8)
        t32[ty + j][tx] = W[(size_t)(k0 + ty + j) * N + n0 + tx];
    __syncthreads();
#pragma unroll
    for (int j = 0; j < 32; j += 8)
        Wt[(size_t)(n0 + ty + j) * K + k0 + tx] =
            __float2bfloat16_rn(t32[tx][ty + j]);
}

__global__ void transpose_all_kernel(
    const float* __restrict__ W1, const float* __restrict__ W2,
    const float* __restrict__ W3, const float* __restrict__ W4,
    __nv_bfloat16* __restrict__ w1t, __nv_bfloat16* __restrict__ w2t,
    __nv_bfloat16* __restrict__ w3t, __nv_bfloat16* __restrict__ w4t) {
    const int tx = threadIdx.x, ty = threadIdx.y;  // 32 x 8
    int b = blockIdx.x;
    if (b < 512) { transpose_tile(W1, w1t, DIM,   H_MID, b, tx, ty); return; }
    b -= 512;
    if (b < 256) { transpose_tile(W2, w2t, H_MID, H_MID, b, tx, ty); return; }
    b -= 256;
    if (b < 128) { transpose_tile(W3, w3t, H_MID, H_LOW, b, tx, ty); return; }
    b -= 128;
    transpose_tile(W4, w4t, H_LOW, DIM, b, tx, ty);
}

// ============================================================================
// LayerNorm: warp-per-row (8 rows per 256-thread block)
// ============================================================================
__global__ void __launch_bounds__(256) ln_kernel(const float* __restrict__ x,
                                                 const float* __restrict__ gamma,
                                                 const float* __restrict__ beta,
                                                 __nv_bfloat16* __restrict__ y) {
    const int tx = threadIdx.x & 31;
    const int ty = threadIdx.x >> 5;
    const int row = blockIdx.x * 8 + ty;
    const float4* xr = reinterpret_cast<const float4*>(x) + (size_t)row * 256;
    float4 v[8];
    float s = 0.f, q = 0.f;
#pragma unroll
    for (int i = 0; i < 8; i++) {
        v[i] = xr[tx + i * 32];
        s += v[i].x + v[i].y + v[i].z + v[i].w;
        q += v[i].x * v[i].x + v[i].y * v[i].y +
             v[i].z * v[i].z + v[i].w * v[i].w;
    }
#pragma unroll
    for (int o = 16; o; o >>= 1) {
        s += __shfl_xor_sync(0xffffffffu, s, o);
        q += __shfl_xor_sync(0xffffffffu, q, o);
    }
    const float mu = s * (1.0f / 1024.0f);
    const float var = q * (1.0f / 1024.0f) - mu * mu;
    const float rstd = rsqrtf(var + 1e-5f);
    uint2* yr = reinterpret_cast<uint2*>(y + (size_t)row * 1024);
#pragma unroll
    for (int i = 0; i < 8; i++) {
        const int c4 = tx + i * 32;
        const float4 g = reinterpret_cast<const float4*>(gamma)[c4];
        const float4 bb = reinterpret_cast<const float4*>(beta)[c4];
        __nv_bfloat162 h01, h23;
        h01.x = __float2bfloat16_rn((v[i].x - mu) * rstd * g.x + bb.x);
        h01.y = __float2bfloat16_rn((v[i].y - mu) * rstd * g.y + bb.y);
        h23.x = __float2bfloat16_rn((v[i].z - mu) * rstd * g.z + bb.z);
        h23.y = __float2bfloat16_rn((v[i].w - mu) * rstd * g.w + bb.w);
        uint2 pk;
        pk.x = *reinterpret_cast<uint32_t*>(&h01);
        pk.y = *reinterpret_cast<uint32_t*>(&h23);
        yr[c4] = pk;
    }
}

// ============================================================================
// bf16 mma.sync GEMM:  C[128x256 tile] = A[M,K] @ Bt[N,K]^T (+bias, epilogue)
//   256 threads, 8 warps (2x4), warp tile 64x64, K-tile 64.
//   3-stage cp.async pipeline, one __syncthreads per K-tile. 1 CTA/SM.
//   RESID=false: out bf16 = gelu(acc + bias)   (feeds next GEMM)
//   RESID=true : out fp32 = acc + bias + resid (final output)
// ============================================================================
static constexpr int PITCH = 144;                       // bytes per smem row
static constexpr int AOFFB = 128 * PITCH;               // A tile bytes (18432)
static constexpr int BOFF = AOFFB;                      // B tile offset in stage
static constexpr int STAGE_BYTES = AOFFB + 256 * PITCH; // 55296
static constexpr int GEMM_SMEM = 3 * STAGE_BYTES;       // 165888

template <bool RESID>
__global__ void __launch_bounds__(256, 1) gemm_bf16_kernel(
    const __nv_bfloat16* __restrict__ A, const __nv_bfloat16* __restrict__ Bt,
    const float* __restrict__ bias, const float* __restrict__ resid,
    void* __restrict__ Cv, int K, int Ntot) {
    extern __shared__ char smem[];
    const uint32_t smem_u = smem_to_u32(smem);
    const int tid = threadIdx.x;
    const int wid = tid >> 5, lane = tid & 31;
    const int wm = wid & 1, wn = wid >> 1;      // 2x4 warps, warp tile 64x64
    const int m0 = blockIdx.x * 128, n0 = blockIdx.y * 256;
    const int NK = K >> 6;                      // K tiles of 64

    const __nv_bfloat16* Abase = A + (size_t)m0 * K;
    const __nv_bfloat16* Bbase = Bt + (size_t)n0 * K;

    const int ldrow = tid >> 3, ldc = (tid & 7) * 16;  // 8 chunks per row
    auto load_tile = [&](int kt, int buf) {
        const uint32_t sb = smem_u + (uint32_t)buf * STAGE_BYTES;
        const int ko = kt * 64;
#pragma unroll
        for (int i = 0; i < 4; i++) {           // A: 128 rows
            const int row = ldrow + i * 32;
            cp_async16(sb + (uint32_t)(row * PITCH) + ldc,
                       Abase + (size_t)row * K + ko + (ldc >> 1));
        }
#pragma unroll
        for (int i = 0; i < 8; i++) {           // B: 256 rows
            const int row = ldrow + i * 32;
            cp_async16(sb + (uint32_t)BOFF + (uint32_t)(row * PITCH) + ldc,
                       Bbase + (size_t)row * K + ko + (ldc >> 1));
        }
        asm volatile("cp.async.commit_group;" ::: "memory");
    };

    float d[4][8][4];
#pragma unroll
    for (int i = 0; i < 4; i++)
#pragma unroll
        for (int j = 0; j < 8; j++)
#pragma unroll
            for (int e = 0; e < 4; e++) d[i][j][e] = 0.0f;

    // A x4 ldsm: rows wm*64 + i*16 + (lane&15), col-halves by lane>=16
    const uint32_t aOff = (uint32_t)((wm * 64 + (lane & 15)) * PITCH +
                                     ((lane >> 4) & 1) * 16);
    // B x4 ldsm: rows wn*64 + j2*16 + (lane&7) + ((lane>>4)&1)*8
    const uint32_t bOff = (uint32_t)BOFF +
        (uint32_t)((wn * 64 + (lane & 7) + ((lane >> 4) & 1) * 8) * PITCH +
                   ((lane >> 3) & 1) * 16);

    load_tile(0, 0);
    load_tile(1, 1);

    for (int kt = 0; kt < NK; kt++) {
        if (kt + 1 < NK) {
            asm volatile("cp.async.wait_group 1;" ::: "memory");
        } else {
            asm volatile("cp.async.wait_group 0;" ::: "memory");
        }
        __syncthreads();
        if (kt + 2 < NK) load_tile(kt + 2, (kt + 2) % 3);

        const uint32_t sb = smem_u + (uint32_t)(kt % 3) * STAGE_BYTES;
#pragma unroll
        for (int ks = 0; ks < 4; ks++) {        // 4 x k16 within the 64-K tile
            uint32_t a[4][4], b[4][4];
#pragma unroll
            for (int i = 0; i < 4; i++)
                ldsm_x4(a[i], sb + aOff + (uint32_t)(i * 16 * PITCH + ks * 32));
#pragma unroll
            for (int j2 = 0; j2 < 4; j2++)
                ldsm_x4(b[j2], sb + bOff + (uint32_t)(j2 * 16 * PITCH + ks * 32));
#pragma unroll
            for (int i = 0; i < 4; i++)
#pragma unroll
                for (int j2 = 0; j2 < 4; j2++) {
                    mma_bf16(d[i][2 * j2],     a[i], b[j2][0], b[j2][1]);
                    mma_bf16(d[i][2 * j2 + 1], a[i], b[j2][2], b[j2][3]);
                }
        }
    }

    // ---- Epilogue ----
    const int g = lane >> 2, t2 = (lane & 3) * 2;
#pragma unroll
    for (int i = 0; i < 4; i++) {
        const int r0 = m0 + wm * 64 + i * 16 + g;
#pragma unroll
        for (int j = 0; j < 8; j++) {
            const int cg = n0 + wn * 64 + j * 8 + t2;
            const float bx = bias[cg], by = bias[cg + 1];
            float v0 = d[i][j][0] + bx, v1 = d[i][j][1] + by;
            float v2 = d[i][j][2] + bx, v3 = d[i][j][3] + by;
            if (RESID) {
                float* C = (float*)Cv;
                const float2 x0 = *reinterpret_cast<const float2*>(
                    resid + (size_t)r0 * Ntot + cg);
                const float2 x1 = *reinterpret_cast<const float2*>(
                    resid + (size_t)(r0 + 8) * Ntot + cg);
                *reinterpret_cast<float2*>(C + (size_t)r0 * Ntot + cg) =
                    make_float2(v0 + x0.x, v1 + x0.y);
                *reinterpret_cast<float2*>(C + (size_t)(r0 + 8) * Ntot + cg) =
                    make_float2(v2 + x1.x, v3 + x1.y);
            } else {
                __nv_bfloat16* C = (__nv_bfloat16*)Cv;
                __nv_bfloat162 p0, p1;
                p0.x = __float2bfloat16_rn(gelu_exact(v0));
                p0.y = __float2bfloat16_rn(gelu_exact(v1));
                p1.x = __float2bfloat16_rn(gelu_exact(v2));
                p1.y = __float2bfloat16_rn(gelu_exact(v3));
                *reinterpret_cast<__nv_bfloat162*>(C + (size_t)r0 * Ntot + cg) = p0;
                *reinterpret_cast<__nv_bfloat162*>(C + (size_t)(r0 + 8) * Ntot + cg) = p1;
            }
        }
    }
}

// ============================================================================
// kernel_launch
// ============================================================================
extern "C" void kernel_launch(void* const* d_in, const int* in_sizes, int n_in,
                              void* d_out, int out_size) {
    const float* x     = (const float*)d_in[0];
    const float* gamma = (const float*)d_in[1];
    const float* beta  = (const float*)d_in[2];
    const float* W1    = (const float*)d_in[3];
    const float* b1    = (const float*)d_in[4];
    const float* W2    = (const float*)d_in[5];
    const float* b2    = (const float*)d_in[6];
    const float* W3    = (const float*)d_in[7];
    const float* b3    = (const float*)d_in[8];
    const float* W4    = (const float*)d_in[9];
    const float* b4    = (const float*)d_in[10];

    __nv_bfloat16 *a0, *a1, *w1t, *w2t, *w3t, *w4t;
    cudaGetSymbolAddress((void**)&a0, g_a0);
    cudaGetSymbolAddress((void**)&a1, g_a1);
    cudaGetSymbolAddress((void**)&w1t, g_w1t);
    cudaGetSymbolAddress((void**)&w2t, g_w2t);
    cudaGetSymbolAddress((void**)&w3t, g_w3t);
    cudaGetSymbolAddress((void**)&w4t, g_w4t);

    cudaFuncSetAttribute(gemm_bf16_kernel<false>,
                         cudaFuncAttributeMaxDynamicSharedMemorySize, GEMM_SMEM);
    cudaFuncSetAttribute(gemm_bf16_kernel<true>,
                         cudaFuncAttributeMaxDynamicSharedMemorySize, GEMM_SMEM);

    transpose_all_kernel<<<1152, dim3(32, 8)>>>(W1, W2, W3, W4,
                                                w1t, w2t, w3t, w4t);
    ln_kernel<<<MTOT / 8, 256>>>(x, gamma, beta, a0);

    // h1 = gelu(ln @ W1 + b1)   (32768 x 512), K=1024
    gemm_bf16_kernel<false><<<dim3(MTOT / 128, H_MID / 256), 256, GEMM_SMEM>>>(
        a0, w1t, b1, nullptr, a1, DIM, H_MID);
    // h2 = gelu(h1 @ W2 + b2)   (32768 x 512), K=512
    gemm_bf16_kernel<false><<<dim3(MTOT / 128, H_MID / 256), 256, GEMM_SMEM>>>(
        a1, w2t, b2, nullptr, a0, H_MID, H_MID);
    // h3 = gelu(h2 @ W3 + b3)   (32768 x 256), K=512
    gemm_bf16_kernel<false><<<dim3(MTOT / 128, H_LOW / 256), 256, GEMM_SMEM>>>(
        a0, w3t, b3, nullptr, a1, H_MID, H_LOW);
    // out = x + h3 @ W4 + b4    (32768 x 1024), K=256
    gemm_bf16_kernel<true><<<dim3(MTOT / 128, DIM / 256), 256, GEMM_SMEM>>>(
        a1, w4t, b4, x, (float*)d_out, H_LOW, DIM);
}

// round 15
// speedup vs baseline: 1.0796x; 1.0796x over previous
#include <cuda_runtime.h>
#include <cuda_bf16.h>
#include <cstdint>
#include <cstddef>

// ============================================================================
// Problem constants and scratch
// ============================================================================
static constexpr int DIM   = 1024;
static constexpr int H_MID = 512;
static constexpr int H_LOW = 256;
static constexpr int MTOT  = 4 * 8192;  // 32768 tokens

__device__ __nv_bfloat16 g_a0[(size_t)MTOT * DIM];    // ln_out, later h2
__device__ __nv_bfloat16 g_a1[(size_t)MTOT * H_MID];  // h1, later h3
__device__ __nv_bfloat16 g_w1t[H_MID * DIM];
__device__ __nv_bfloat16 g_w2t[H_MID * H_MID];
__device__ __nv_bfloat16 g_w3t[H_LOW * H_MID];
__device__ __nv_bfloat16 g_w4t[DIM * H_LOW];

// ============================================================================
// Helpers
// ============================================================================
__device__ __forceinline__ float gelu_exact(float v) {
    return 0.5f * v * (1.0f + erff(v * 0.70710678118654752440f));
}

__device__ __forceinline__ uint32_t smem_to_u32(const void* p) {
    uint32_t a;
    asm("{ .reg .u64 t; cvta.to.shared.u64 t, %1; cvt.u32.u64 %0, t; }"
        : "=r"(a) : "l"(p));
    return a;
}

__device__ __forceinline__ void cp_async16(uint32_t s, const void* g) {
    asm volatile("cp.async.cg.shared.global [%0], [%1], 16;" :: "r"(s), "l"(g));
}

__device__ __forceinline__ void ldsm_x4(uint32_t (&r)[4], uint32_t addr) {
    asm volatile("ldmatrix.sync.aligned.m8n8.x4.shared.b16 {%0,%1,%2,%3}, [%4];"
                 : "=r"(r[0]), "=r"(r[1]), "=r"(r[2]), "=r"(r[3]) : "r"(addr));
}

__device__ __forceinline__ void mma_bf16(float (&d)[4], const uint32_t (&a)[4],
                                         uint32_t b0, uint32_t b1) {
    asm volatile(
        "mma.sync.aligned.m16n8k16.row.col.f32.bf16.bf16.f32 "
        "{%0,%1,%2,%3},{%4,%5,%6,%7},{%8,%9},{%0,%1,%2,%3};"
        : "+f"(d[0]), "+f"(d[1]), "+f"(d[2]), "+f"(d[3])
        : "r"(a[0]), "r"(a[1]), "r"(a[2]), "r"(a[3]), "r"(b0), "r"(b1));
}

// ============================================================================
// All-weights transpose + bf16 round:  W[K,N] fp32 -> Wt[N,K] bf16
// ============================================================================
__device__ __forceinline__ void transpose_tile(const float* __restrict__ W,
                                               __nv_bfloat16* __restrict__ Wt,
                                               int K, int N, int tile,
                                               int tx, int ty) {
    __shared__ float t32[32][33];
    const int tilesX = N >> 5;
    const int n0 = (tile % tilesX) * 32, k0 = (tile / tilesX) * 32;
#pragma unroll
    for (int j = 0; j < 32; j += 8)
        t32[ty + j][tx] = W[(size_t)(k0 + ty + j) * N + n0 + tx];
    __syncthreads();
#pragma unroll
    for (int j = 0; j < 32; j += 8)
        Wt[(size_t)(n0 + ty + j) * K + k0 + tx] =
            __float2bfloat16_rn(t32[tx][ty + j]);
}

__global__ void transpose_all_kernel(
    const float* __restrict__ W1, const float* __restrict__ W2,
    const float* __restrict__ W3, const float* __restrict__ W4,
    __nv_bfloat16* __restrict__ w1t, __nv_bfloat16* __restrict__ w2t,
    __nv_bfloat16* __restrict__ w3t, __nv_bfloat16* __restrict__ w4t) {
    const int tx = threadIdx.x, ty = threadIdx.y;  // 32 x 8
    int b = blockIdx.x;
    if (b < 512) { transpose_tile(W1, w1t, DIM,   H_MID, b, tx, ty); return; }
    b -= 512;
    if (b < 256) { transpose_tile(W2, w2t, H_MID, H_MID, b, tx, ty); return; }
    b -= 256;
    if (b < 128) { transpose_tile(W3, w3t, H_MID, H_LOW, b, tx, ty); return; }
    b -= 128;
    transpose_tile(W4, w4t, H_LOW, DIM, b, tx, ty);
}

// ============================================================================
// LayerNorm: warp-per-row (8 rows per 256-thread block)
// ============================================================================
__global__ void __launch_bounds__(256) ln_kernel(const float* __restrict__ x,
                                                 const float* __restrict__ gamma,
                                                 const float* __restrict__ beta,
                                                 __nv_bfloat16* __restrict__ y) {
    const int tx = threadIdx.x & 31;
    const int ty = threadIdx.x >> 5;
    const int row = blockIdx.x * 8 + ty;
    const float4* xr = reinterpret_cast<const float4*>(x) + (size_t)row * 256;
    float4 v[8];
    float s = 0.f, q = 0.f;
#pragma unroll
    for (int i = 0; i < 8; i++) {
        v[i] = xr[tx + i * 32];
        s += v[i].x + v[i].y + v[i].z + v[i].w;
        q += v[i].x * v[i].x + v[i].y * v[i].y +
             v[i].z * v[i].z + v[i].w * v[i].w;
    }
#pragma unroll
    for (int o = 16; o; o >>= 1) {
        s += __shfl_xor_sync(0xffffffffu, s, o);
        q += __shfl_xor_sync(0xffffffffu, q, o);
    }
    const float mu = s * (1.0f / 1024.0f);
    const float var = q * (1.0f / 1024.0f) - mu * mu;
    const float rstd = rsqrtf(var + 1e-5f);
    uint2* yr = reinterpret_cast<uint2*>(y + (size_t)row * 1024);
#pragma unroll
    for (int i = 0; i < 8; i++) {
        const int c4 = tx + i * 32;
        const float4 g = reinterpret_cast<const float4*>(gamma)[c4];
        const float4 bb = reinterpret_cast<const float4*>(beta)[c4];
        __nv_bfloat162 h01, h23;
        h01.x = __float2bfloat16_rn((v[i].x - mu) * rstd * g.x + bb.x);
        h01.y = __float2bfloat16_rn((v[i].y - mu) * rstd * g.y + bb.y);
        h23.x = __float2bfloat16_rn((v[i].z - mu) * rstd * g.z + bb.z);
        h23.y = __float2bfloat16_rn((v[i].w - mu) * rstd * g.w + bb.w);
        uint2 pk;
        pk.x = *reinterpret_cast<uint32_t*>(&h01);
        pk.y = *reinterpret_cast<uint32_t*>(&h23);
        yr[c4] = pk;
    }
}

// ============================================================================
// bf16 mma.sync GEMM:  C[128x128 tile] = A[M,K] @ Bt[N,K]^T (+bias, epilogue)
//   128 threads, 4 warps (2x2), warp tile 64x64, K-tile 64.
//   3-stage cp.async pipeline; 2 CTAs/SM (independent barriers -> hiding).
//   RESID=false: out bf16 = gelu(acc + bias)   (feeds next GEMM)
//   RESID=true : out fp32 = acc + bias + resid (final output)
// ============================================================================
static constexpr int PITCH = 144;                       // bytes per smem row
static constexpr int BOFF = 128 * PITCH;                // B tile offset in stage
static constexpr int STAGE_BYTES = 2 * 128 * PITCH;     // 36864
static constexpr int GEMM_SMEM = 3 * STAGE_BYTES;       // 110592

template <bool RESID>
__global__ void __launch_bounds__(128, 2) gemm_bf16_kernel(
    const __nv_bfloat16* __restrict__ A, const __nv_bfloat16* __restrict__ Bt,
    const float* __restrict__ bias, const float* __restrict__ resid,
    void* __restrict__ Cv, int K, int Ntot) {
    extern __shared__ char smem[];
    const uint32_t smem_u = smem_to_u32(smem);
    const int tid = threadIdx.x;
    const int wid = tid >> 5, lane = tid & 31;
    const int wm = wid & 1, wn = wid >> 1;      // 2x2 warps, warp tile 64x64
    const int m0 = blockIdx.x * 128, n0 = blockIdx.y * 128;
    const int NK = K >> 6;                      // K tiles of 64

    const __nv_bfloat16* Abase = A + (size_t)m0 * K;
    const __nv_bfloat16* Bbase = Bt + (size_t)n0 * K;

    const int ldrow = tid >> 3, ldc = (tid & 7) * 16;  // 16 rows per pass
    auto load_tile = [&](int kt, int buf) {
        const uint32_t sb = smem_u + (uint32_t)buf * STAGE_BYTES;
        const int ko = kt * 64;
#pragma unroll
        for (int i = 0; i < 8; i++) {           // A: 128 rows
            const int row = ldrow + i * 16;
            cp_async16(sb + (uint32_t)(row * PITCH) + ldc,
                       Abase + (size_t)row * K + ko + (ldc >> 1));
        }
#pragma unroll
        for (int i = 0; i < 8; i++) {           // B: 128 rows
            const int row = ldrow + i * 16;
            cp_async16(sb + (uint32_t)BOFF + (uint32_t)(row * PITCH) + ldc,
                       Bbase + (size_t)row * K + ko + (ldc >> 1));
        }
        asm volatile("cp.async.commit_group;" ::: "memory");
    };

    float d[4][8][4];
#pragma unroll
    for (int i = 0; i < 4; i++)
#pragma unroll
        for (int j = 0; j < 8; j++)
#pragma unroll
            for (int e = 0; e < 4; e++) d[i][j][e] = 0.0f;

    // A x4 ldsm: rows wm*64 + i*16 + (lane&15), col-half by lane>=16
    const uint32_t aOff = (uint32_t)((wm * 64 + (lane & 15)) * PITCH +
                                     ((lane >> 4) & 1) * 16);
    // B x4 ldsm: rows wn*64 + j2*16 + (lane&7) + ((lane>>4)&1)*8
    const uint32_t bOff = (uint32_t)BOFF +
        (uint32_t)((wn * 64 + (lane & 7) + ((lane >> 4) & 1) * 8) * PITCH +
                   ((lane >> 3) & 1) * 16);

    load_tile(0, 0);
    load_tile(1, 1);

    for (int kt = 0; kt < NK; kt++) {
        if (kt + 1 < NK) {
            asm volatile("cp.async.wait_group 1;" ::: "memory");
        } else {
            asm volatile("cp.async.wait_group 0;" ::: "memory");
        }
        __syncthreads();
        if (kt + 2 < NK) load_tile(kt + 2, (kt + 2) % 3);

        const uint32_t sb = smem_u + (uint32_t)(kt % 3) * STAGE_BYTES;
#pragma unroll
        for (int ks = 0; ks < 4; ks++) {        // 4 x k16 within the 64-K tile
            uint32_t a[4][4], b[4][4];
#pragma unroll
            for (int i = 0; i < 4; i++)
                ldsm_x4(a[i], sb + aOff + (uint32_t)(i * 16 * PITCH + ks * 32));
#pragma unroll
            for (int j2 = 0; j2 < 4; j2++)
                ldsm_x4(b[j2], sb + bOff + (uint32_t)(j2 * 16 * PITCH + ks * 32));
#pragma unroll
            for (int i = 0; i < 4; i++)
#pragma unroll
                for (int j2 = 0; j2 < 4; j2++) {
                    mma_bf16(d[i][2 * j2],     a[i], b[j2][0], b[j2][1]);
                    mma_bf16(d[i][2 * j2 + 1], a[i], b[j2][2], b[j2][3]);
                }
        }
    }

    // ---- Epilogue ----
    const int g = lane >> 2, t2 = (lane & 3) * 2;
#pragma unroll
    for (int i = 0; i < 4; i++) {
        const int r0 = m0 + wm * 64 + i * 16 + g;
#pragma unroll
        for (int j = 0; j < 8; j++) {
            const int cg = n0 + wn * 64 + j * 8 + t2;
            const float bx = bias[cg], by = bias[cg + 1];
            float v0 = d[i][j][0] + bx, v1 = d[i][j][1] + by;
            float v2 = d[i][j][2] + bx, v3 = d[i][j][3] + by;
            if (RESID) {
                float* C = (float*)Cv;
                const float2 x0 = *reinterpret_cast<const float2*>(
                    resid + (size_t)r0 * Ntot + cg);
                const float2 x1 = *reinterpret_cast<const float2*>(
                    resid + (size_t)(r0 + 8) * Ntot + cg);
                *reinterpret_cast<float2*>(C + (size_t)r0 * Ntot + cg) =
                    make_float2(v0 + x0.x, v1 + x0.y);
                *reinterpret_cast<float2*>(C + (size_t)(r0 + 8) * Ntot + cg) =
                    make_float2(v2 + x1.x, v3 + x1.y);
            } else {
                __nv_bfloat16* C = (__nv_bfloat16*)Cv;
                __nv_bfloat162 p0, p1;
                p0.x = __float2bfloat16_rn(gelu_exact(v0));
                p0.y = __float2bfloat16_rn(gelu_exact(v1));
                p1.x = __float2bfloat16_rn(gelu_exact(v2));
                p1.y = __float2bfloat16_rn(gelu_exact(v3));
                *reinterpret_cast<__nv_bfloat162*>(C + (size_t)r0 * Ntot + cg) = p0;
                *reinterpret_cast<__nv_bfloat162*>(C + (size_t)(r0 + 8) * Ntot + cg) = p1;
            }
        }
    }
}

// ============================================================================
// kernel_launch
// ============================================================================
extern "C" void kernel_launch(void* const* d_in, const int* in_sizes, int n_in,
                              void* d_out, int out_size) {
    const float* x     = (const float*)d_in[0];
    const float* gamma = (const float*)d_in[1];
    const float* beta  = (const float*)d_in[2];
    const float* W1    = (const float*)d_in[3];
    const float* b1    = (const float*)d_in[4];
    const float* W2    = (const float*)d_in[5];
    const float* b2    = (const float*)d_in[6];
    const float* W3    = (const float*)d_in[7];
    const float* b3    = (const float*)d_in[8];
    const float* W4    = (const float*)d_in[9];
    const float* b4    = (const float*)d_in[10];

    __nv_bfloat16 *a0, *a1, *w1t, *w2t, *w3t, *w4t;
    cudaGetSymbolAddress((void**)&a0, g_a0);
    cudaGetSymbolAddress((void**)&a1, g_a1);
    cudaGetSymbolAddress((void**)&w1t, g_w1t);
    cudaGetSymbolAddress((void**)&w2t, g_w2t);
    cudaGetSymbolAddress((void**)&w3t, g_w3t);
    cudaGetSymbolAddress((void**)&w4t, g_w4t);

    cudaFuncSetAttribute(gemm_bf16_kernel<false>,
                         cudaFuncAttributeMaxDynamicSharedMemorySize, GEMM_SMEM);
    cudaFuncSetAttribute(gemm_bf16_kernel<true>,
                         cudaFuncAttributeMaxDynamicSharedMemorySize, GEMM_SMEM);

    transpose_all_kernel<<<1152, dim3(32, 8)>>>(W1, W2, W3, W4,
                                                w1t, w2t, w3t, w4t);
    ln_kernel<<<MTOT / 8, 256>>>(x, gamma, beta, a0);

    // h1 = gelu(ln @ W1 + b1)   (32768 x 512), K=1024
    gemm_bf16_kernel<false><<<dim3(MTOT / 128, H_MID / 128), 128, GEMM_SMEM>>>(
        a0, w1t, b1, nullptr, a1, DIM, H_MID);
    // h2 = gelu(h1 @ W2 + b2)   (32768 x 512), K=512
    gemm_bf16_kernel<false><<<dim3(MTOT / 128, H_MID / 128), 128, GEMM_SMEM>>>(
        a1, w2t, b2, nullptr, a0, H_MID, H_MID);
    // h3 = gelu(h2 @ W3 + b3)   (32768 x 256), K=512
    gemm_bf16_kernel<false><<<dim3(MTOT / 128, H_LOW / 128), 128, GEMM_SMEM>>>(
        a0, w3t, b3, nullptr, a1, H_MID, H_LOW);
    // out = x + h3 @ W4 + b4    (32768 x 1024), K=256
    gemm_bf16_kernel<true><<<dim3(MTOT / 128, DIM / 128), 128, GEMM_SMEM>>>(
        a1, w4t, b4, x, (float*)d_out, H_LOW, DIM);
}

// round 17
// speedup vs baseline: 1.2087x; 1.1196x over previous
#include <cuda_runtime.h>
#include <cuda_bf16.h>
#include <cstdint>
#include <cstddef>

// ============================================================================
// Problem constants and scratch
// ============================================================================
static constexpr int DIM   = 1024;
static constexpr int H_MID = 512;
static constexpr int H_LOW = 256;
static constexpr int MTOT  = 4 * 8192;  // 32768 tokens

__device__ __nv_bfloat16 g_a0[(size_t)MTOT * DIM];    // ln_out, later h2
__device__ __nv_bfloat16 g_a1[(size_t)MTOT * H_MID];  // h1, later h3
__device__ __nv_bfloat16 g_w1t[H_MID * DIM];
__device__ __nv_bfloat16 g_w2t[H_MID * H_MID];
__device__ __nv_bfloat16 g_w3t[H_LOW * H_MID];
__device__ __nv_bfloat16 g_w4t[DIM * H_LOW];

// ============================================================================
// Helpers
// ============================================================================
__device__ __forceinline__ float gelu_exact(float v) {
    return 0.5f * v * (1.0f + erff(v * 0.70710678118654752440f));
}

__device__ __forceinline__ uint32_t smem_to_u32(const void* p) {
    uint32_t a;
    asm("{ .reg .u64 t; cvta.to.shared.u64 t, %1; cvt.u32.u64 %0, t; }"
        : "=r"(a) : "l"(p));
    return a;
}

__device__ __forceinline__ void cp_async16(uint32_t s, const void* g) {
    asm volatile("cp.async.cg.shared.global [%0], [%1], 16;" :: "r"(s), "l"(g));
}

__device__ __forceinline__ void ldsm_x4(uint32_t (&r)[4], uint32_t addr) {
    asm volatile("ldmatrix.sync.aligned.m8n8.x4.shared.b16 {%0,%1,%2,%3}, [%4];"
                 : "=r"(r[0]), "=r"(r[1]), "=r"(r[2]), "=r"(r[3]) : "r"(addr));
}

__device__ __forceinline__ void mma_bf16(float (&d)[4], const uint32_t (&a)[4],
                                         uint32_t b0, uint32_t b1) {
    asm volatile(
        "mma.sync.aligned.m16n8k16.row.col.f32.bf16.bf16.f32 "
        "{%0,%1,%2,%3},{%4,%5,%6,%7},{%8,%9},{%0,%1,%2,%3};"
        : "+f"(d[0]), "+f"(d[1]), "+f"(d[2]), "+f"(d[3])
        : "r"(a[0]), "r"(a[1]), "r"(a[2]), "r"(a[3]), "r"(b0), "r"(b1));
}

// ============================================================================
// All-weights transpose + bf16 round:  W[K,N] fp32 -> Wt[N,K] bf16
// ============================================================================
__device__ __forceinline__ void transpose_tile(const float* __restrict__ W,
                                               __nv_bfloat16* __restrict__ Wt,
                                               int K, int N, int tile,
                                               int tx, int ty) {
    __shared__ float t32[32][33];
    const int tilesX = N >> 5;
    const int n0 = (tile % tilesX) * 32, k0 = (tile / tilesX) * 32;
#pragma unroll
    for (int j = 0; j < 32; j += 8)
        t32[ty + j][tx] = W[(size_t)(k0 + ty + j) * N + n0 + tx];
    __syncthreads();
#pragma unroll
    for (int j = 0; j < 32; j += 8)
        Wt[(size_t)(n0 + ty + j) * K + k0 + tx] =
            __float2bfloat16_rn(t32[tx][ty + j]);
}

__global__ void transpose_all_kernel(
    const float* __restrict__ W1, const float* __restrict__ W2,
    const float* __restrict__ W3, const float* __restrict__ W4,
    __nv_bfloat16* __restrict__ w1t, __nv_bfloat16* __restrict__ w2t,
    __nv_bfloat16* __restrict__ w3t, __nv_bfloat16* __restrict__ w4t) {
    const int tx = threadIdx.x, ty = threadIdx.y;  // 32 x 8
    int b = blockIdx.x;
    if (b < 512) { transpose_tile(W1, w1t, DIM,   H_MID, b, tx, ty); return; }
    b -= 512;
    if (b < 256) { transpose_tile(W2, w2t, H_MID, H_MID, b, tx, ty); return; }
    b -= 256;
    if (b < 128) { transpose_tile(W3, w3t, H_MID, H_LOW, b, tx, ty); return; }
    b -= 128;
    transpose_tile(W4, w4t, H_LOW, DIM, b, tx, ty);
}

// ============================================================================
// LayerNorm: warp-per-row (8 rows per 256-thread block)
// ============================================================================
__global__ void __launch_bounds__(256) ln_kernel(const float* __restrict__ x,
                                                 const float* __restrict__ gamma,
                                                 const float* __restrict__ beta,
                                                 __nv_bfloat16* __restrict__ y) {
    const int tx = threadIdx.x & 31;
    const int ty = threadIdx.x >> 5;
    const int row = blockIdx.x * 8 + ty;
    const float4* xr = reinterpret_cast<const float4*>(x) + (size_t)row * 256;
    float4 v[8];
    float s = 0.f, q = 0.f;
#pragma unroll
    for (int i = 0; i < 8; i++) {
        v[i] = xr[tx + i * 32];
        s += v[i].x + v[i].y + v[i].z + v[i].w;
        q += v[i].x * v[i].x + v[i].y * v[i].y +
             v[i].z * v[i].z + v[i].w * v[i].w;
    }
#pragma unroll
    for (int o = 16; o; o >>= 1) {
        s += __shfl_xor_sync(0xffffffffu, s, o);
        q += __shfl_xor_sync(0xffffffffu, q, o);
    }
    const float mu = s * (1.0f / 1024.0f);
    const float var = q * (1.0f / 1024.0f) - mu * mu;
    const float rstd = rsqrtf(var + 1e-5f);
    uint2* yr = reinterpret_cast<uint2*>(y + (size_t)row * 1024);
#pragma unroll
    for (int i = 0; i < 8; i++) {
        const int c4 = tx + i * 32;
        const float4 g = reinterpret_cast<const float4*>(gamma)[c4];
        const float4 bb = reinterpret_cast<const float4*>(beta)[c4];
        __nv_bfloat162 h01, h23;
        h01.x = __float2bfloat16_rn((v[i].x - mu) * rstd * g.x + bb.x);
        h01.y = __float2bfloat16_rn((v[i].y - mu) * rstd * g.y + bb.y);
        h23.x = __float2bfloat16_rn((v[i].z - mu) * rstd * g.z + bb.z);
        h23.y = __float2bfloat16_rn((v[i].w - mu) * rstd * g.w + bb.w);
        uint2 pk;
        pk.x = *reinterpret_cast<uint32_t*>(&h01);
        pk.y = *reinterpret_cast<uint32_t*>(&h23);
        yr[c4] = pk;
    }
}

// ============================================================================
// bf16 mma.sync GEMM:  C[128x128 tile] = A[M,K] @ Bt[N,K]^T (+bias, epilogue)
//   256 threads, 8 warps (4x2), warp tile 32x64, K-tile 64.
//   3-stage cp.async pipeline, one __syncthreads per K-tile.
//   Convoy fix: after the barrier, compute ks=0 FIRST, then issue the
//   kt+2 prefetch, then ks=1..3 — MMAs start immediately post-barrier and
//   the LDGSTS burst hides under tensor work.
//   RESID=false: out bf16 = gelu(acc + bias)   (feeds next GEMM)
//   RESID=true : out fp32 = acc + bias + resid (final output)
// ============================================================================
static constexpr int PITCH = 144;                       // bytes per smem row
static constexpr int BOFF = 128 * PITCH;                // B tile offset in stage
static constexpr int STAGE_BYTES = 2 * 128 * PITCH;     // 36864
static constexpr int GEMM_SMEM = 3 * STAGE_BYTES;       // 110592

template <bool RESID>
__global__ void __launch_bounds__(256, 2) gemm_bf16_kernel(
    const __nv_bfloat16* __restrict__ A, const __nv_bfloat16* __restrict__ Bt,
    const float* __restrict__ bias, const float* __restrict__ resid,
    void* __restrict__ Cv, int K, int Ntot) {
    extern __shared__ char smem[];
    const uint32_t smem_u = smem_to_u32(smem);
    const int tid = threadIdx.x;
    const int wid = tid >> 5, lane = tid & 31;
    const int wm = wid & 3, wn = wid >> 2;      // 4x2 warps, warp tile 32x64
    const int m0 = blockIdx.x * 128, n0 = blockIdx.y * 128;
    const int NK = K >> 6;                      // K tiles of 64

    const __nv_bfloat16* Abase = A + (size_t)m0 * K;
    const __nv_bfloat16* Bbase = Bt + (size_t)n0 * K;

    const int ldrow = tid >> 3, ldc = (tid & 7) * 16;  // ldc in bytes (8 bf16)
    auto load_tile = [&](int kt, int buf) {
        const uint32_t sb = smem_u + (uint32_t)buf * STAGE_BYTES;
        const int ko = kt * 64;
#pragma unroll
        for (int i = 0; i < 4; i++) {
            const int row = ldrow + i * 32;
            cp_async16(sb + (uint32_t)(row * PITCH) + ldc,
                       Abase + (size_t)row * K + ko + (ldc >> 1));
        }
#pragma unroll
        for (int i = 0; i < 4; i++) {
            const int row = ldrow + i * 32;
            cp_async16(sb + (uint32_t)BOFF + (uint32_t)(row * PITCH) + ldc,
                       Bbase + (size_t)row * K + ko + (ldc >> 1));
        }
        asm volatile("cp.async.commit_group;" ::: "memory");
    };

    float d[2][8][4];
#pragma unroll
    for (int i = 0; i < 2; i++)
#pragma unroll
        for (int j = 0; j < 8; j++)
#pragma unroll
            for (int e = 0; e < 4; e++) d[i][j][e] = 0.0f;

    const uint32_t aOff = (uint32_t)((wm * 32 + (lane & 15)) * PITCH +
                                     ((lane >> 4) & 1) * 16);
    const uint32_t bOff = (uint32_t)BOFF +
        (uint32_t)((wn * 64 + (lane & 7) + ((lane >> 4) & 1) * 8) * PITCH +
                   ((lane >> 3) & 1) * 16);

    // One ks-step (k16) of ldsm + mma from stage base sb.
    auto compute_ks = [&](uint32_t sb, int ks) {
        uint32_t a[2][4], b[4][4];
#pragma unroll
        for (int i = 0; i < 2; i++)
            ldsm_x4(a[i], sb + aOff + (uint32_t)(i * 16 * PITCH + ks * 32));
#pragma unroll
        for (int j2 = 0; j2 < 4; j2++)
            ldsm_x4(b[j2], sb + bOff + (uint32_t)(j2 * 16 * PITCH + ks * 32));
#pragma unroll
        for (int i = 0; i < 2; i++)
#pragma unroll
            for (int j2 = 0; j2 < 4; j2++) {
                mma_bf16(d[i][2 * j2],     a[i], b[j2][0], b[j2][1]);
                mma_bf16(d[i][2 * j2 + 1], a[i], b[j2][2], b[j2][3]);
            }
    };

    load_tile(0, 0);
    load_tile(1, 1);

    for (int kt = 0; kt < NK; kt++) {
        if (kt + 1 < NK) {
            asm volatile("cp.async.wait_group 1;" ::: "memory");
        } else {
            asm volatile("cp.async.wait_group 0;" ::: "memory");
        }
        __syncthreads();
        const uint32_t sb = smem_u + (uint32_t)(kt % 3) * STAGE_BYTES;

        // Start the tensor pipe immediately after the barrier...
        compute_ks(sb, 0);
        // ...then bury the next-tile global loads under MMA work.
        if (kt + 2 < NK) load_tile(kt + 2, (kt + 2) % 3);
        compute_ks(sb, 1);
        compute_ks(sb, 2);
        compute_ks(sb, 3);
    }

    // ---- Epilogue ----
    const int g = lane >> 2, t2 = (lane & 3) * 2;
#pragma unroll
    for (int i = 0; i < 2; i++) {
        const int r0 = m0 + wm * 32 + i * 16 + g;
#pragma unroll
        for (int j = 0; j < 8; j++) {
            const int cg = n0 + wn * 64 + j * 8 + t2;
            const float bx = bias[cg], by = bias[cg + 1];
            float v0 = d[i][j][0] + bx, v1 = d[i][j][1] + by;
            float v2 = d[i][j][2] + bx, v3 = d[i][j][3] + by;
            if (RESID) {
                float* C = (float*)Cv;
                const float2 x0 = *reinterpret_cast<const float2*>(
                    resid + (size_t)r0 * Ntot + cg);
                const float2 x1 = *reinterpret_cast<const float2*>(
                    resid + (size_t)(r0 + 8) * Ntot + cg);
                *reinterpret_cast<float2*>(C + (size_t)r0 * Ntot + cg) =
                    make_float2(v0 + x0.x, v1 + x0.y);
                *reinterpret_cast<float2*>(C + (size_t)(r0 + 8) * Ntot + cg) =
                    make_float2(v2 + x1.x, v3 + x1.y);
            } else {
                __nv_bfloat16* C = (__nv_bfloat16*)Cv;
                __nv_bfloat162 p0, p1;
                p0.x = __float2bfloat16_rn(gelu_exact(v0));
                p0.y = __float2bfloat16_rn(gelu_exact(v1));
                p1.x = __float2bfloat16_rn(gelu_exact(v2));
                p1.y = __float2bfloat16_rn(gelu_exact(v3));
                *reinterpret_cast<__nv_bfloat162*>(C + (size_t)r0 * Ntot + cg) = p0;
                *reinterpret_cast<__nv_bfloat162*>(C + (size_t)(r0 + 8) * Ntot + cg) = p1;
            }
        }
    }
}

// ============================================================================
// kernel_launch
// ============================================================================
extern "C" void kernel_launch(void* const* d_in, const int* in_sizes, int n_in,
                              void* d_out, int out_size) {
    const float* x     = (const float*)d_in[0];
    const float* gamma = (const float*)d_in[1];
    const float* beta  = (const float*)d_in[2];
    const float* W1    = (const float*)d_in[3];
    const float* b1    = (const float*)d_in[4];
    const float* W2    = (const float*)d_in[5];
    const float* b2    = (const float*)d_in[6];
    const float* W3    = (const float*)d_in[7];
    const float* b3    = (const float*)d_in[8];
    const float* W4    = (const float*)d_in[9];
    const float* b4    = (const float*)d_in[10];

    __nv_bfloat16 *a0, *a1, *w1t, *w2t, *w3t, *w4t;
    cudaGetSymbolAddress((void**)&a0, g_a0);
    cudaGetSymbolAddress((void**)&a1, g_a1);
    cudaGetSymbolAddress((void**)&w1t, g_w1t);
    cudaGetSymbolAddress((void**)&w2t, g_w2t);
    cudaGetSymbolAddress((void**)&w3t, g_w3t);
    cudaGetSymbolAddress((void**)&w4t, g_w4t);

    cudaFuncSetAttribute(gemm_bf16_kernel<false>,
                         cudaFuncAttributeMaxDynamicSharedMemorySize, GEMM_SMEM);
    cudaFuncSetAttribute(gemm_bf16_kernel<true>,
                         cudaFuncAttributeMaxDynamicSharedMemorySize, GEMM_SMEM);

    transpose_all_kernel<<<1152, dim3(32, 8)>>>(W1, W2, W3, W4,
                                                w1t, w2t, w3t, w4t);
    ln_kernel<<<MTOT / 8, 256>>>(x, gamma, beta, a0);

    // h1 = gelu(ln @ W1 + b1)   (32768 x 512), K=1024
    gemm_bf16_kernel<false><<<dim3(MTOT / 128, H_MID / 128), 256, GEMM_SMEM>>>(
        a0, w1t, b1, nullptr, a1, DIM, H_MID);
    // h2 = gelu(h1 @ W2 + b2)   (32768 x 512), K=512
    gemm_bf16_kernel<false><<<dim3(MTOT / 128, H_MID / 128), 256, GEMM_SMEM>>>(
        a1, w2t, b2, nullptr, a0, H_MID, H_MID);
    // h3 = gelu(h2 @ W3 + b3)   (32768 x 256), K=512
    gemm_bf16_kernel<false><<<dim3(MTOT / 128, H_LOW / 128), 256, GEMM_SMEM>>>(
        a0, w3t, b3, nullptr, a1, H_MID, H_LOW);
    // out = x + h3 @ W4 + b4    (32768 x 1024), K=256
    gemm_bf16_kernel<true><<<dim3(MTOT / 128, DIM / 128), 256, GEMM_SMEM>>>(
        a1, w4t, b4, x, (float*)d_out, H_LOW, DIM);
}